// round 4
// baseline (speedup 1.0000x reference)
#include <cuda_runtime.h>
#include <cstdint>

#define BATCH 512
#define SEQ   512
#define OBS   103
#define HID   512
#define INP   105            // OBS + 2 fed-back pos
#define KTOT  617            // INP + HID
#define GAT   2048           // 4*HID
#define NBLK  128
#define NTHR  256
#define PITCH 36             // smem k-row pitch (16B-aligned LDS.128)
#define OFF_H (BATCH*SEQ*2)
#define OFF_C (OFF_H + BATCH*HID)
#define SMEM_FLOATS (KTOT*PITCH + 576)
#define SMEM_BYTES  (SMEM_FLOATS*4)

typedef unsigned long long ull;

// ---- static device scratch (no allocation allowed) ----
__device__ __align__(16) float g_Wt[KTOT*GAT];   // k-major, gate-interleaved cols
__device__ __align__(16) float g_bias[GAT];      // b_ih+b_hh, permuted
__device__ __align__(16) float g_hbuf[2][BATCH*HID];
__device__ __align__(16) float g_y[BATCH*2];
__device__ unsigned g_arrive;
__device__ volatile unsigned g_gen;

// ---- packed f32x2 helpers ----
__device__ __forceinline__ ull dup2(float x) {
    ull r; asm("mov.b64 %0, {%1, %1};" : "=l"(r) : "f"(x)); return r;
}
__device__ __forceinline__ ull pack2(float lo, float hi) {
    ull r; asm("mov.b64 %0, {%1, %2};" : "=l"(r) : "f"(lo), "f"(hi)); return r;
}
__device__ __forceinline__ float2 unpack2(ull v) {
    float lo, hi; asm("mov.b64 {%0, %1}, %2;" : "=f"(lo), "=f"(hi) : "l"(v));
    return make_float2(lo, hi);
}
__device__ __forceinline__ void fma2(ull &d, ull a, ull b) {
    asm("fma.rn.f32x2 %0, %1, %2, %0;" : "+l"(d) : "l"(a), "l"(b));
}

__device__ __forceinline__ float sigm(float x) { return 1.f / (1.f + __expf(-x)); }
__device__ __forceinline__ float tanh_(float x) {
    x = fminf(15.f, fmaxf(-15.f, x));
    float e = __expf(-2.f * x);
    return (1.f - e) / (1.f + e);
}

// ---- grid barrier: all 128 blocks co-resident -> spin is safe ----
__device__ __forceinline__ void grid_barrier(unsigned target) {
    __threadfence();
    __syncthreads();
    if (threadIdx.x == 0) {
        unsigned v = atomicAdd(&g_arrive, 1u);
        if (v == NBLK - 1) {
            g_arrive = 0;
            __threadfence();
            g_gen = target;
        } else {
            while (g_gen < target) __nanosleep(64);
        }
    }
    __syncthreads();
}

// ---- precompute: permuted transpose of W, combined bias, state init ----
__global__ void precompute_kernel(const float* __restrict__ W_ih,
                                  const float* __restrict__ W_hh,
                                  const float* __restrict__ b_ih,
                                  const float* __restrict__ b_hh,
                                  const float* __restrict__ hidden,
                                  const float* __restrict__ pos) {
    const int stride = gridDim.x * blockDim.x;
    const int i0 = blockIdx.x * blockDim.x + threadIdx.x;
    // Wt[k][col]; col = ubp*256 + ul*4 + g  <->  original row r = g*HID + ubp*64 + ul
    for (int idx = i0; idx < KTOT * GAT; idx += stride) {
        int k = idx >> 11, col = idx & 2047;
        int ubp = col >> 8, rem = col & 255, ul = rem >> 2, g = rem & 3;
        int r = g * HID + ubp * 64 + ul;
        g_Wt[idx] = (k < INP) ? W_ih[r * INP + k] : W_hh[r * HID + (k - INP)];
    }
    for (int col = i0; col < GAT; col += stride) {
        int ubp = col >> 8, rem = col & 255, ul = rem >> 2, g = rem & 3;
        int r = g * HID + ubp * 64 + ul;
        g_bias[col] = b_ih[r] + b_hh[r];
    }
    for (int idx = i0; idx < BATCH * HID; idx += stride) g_hbuf[0][idx] = hidden[idx];
    for (int idx = i0; idx < BATCH * 2; idx += stride)
        g_y[idx] = pos[(idx >> 1) * SEQ * 2 + (idx & 1)];   // pos[:,0,:]
    if (i0 == 0) { g_arrive = 0; g_gen = 0; }
}

// ---- persistent LSTM kernel ----
__global__ void __launch_bounds__(NTHR, 1)
lstm_persistent(const float* __restrict__ x,
                const float* __restrict__ cell,
                const float* __restrict__ W1, const float* __restrict__ b1,
                const float* __restrict__ W2, const float* __restrict__ b2,
                const float* __restrict__ W3, const float* __restrict__ b3,
                float* __restrict__ out) {
    extern __shared__ float sm[];
    float* sa  = sm;                       // staged input, k-major [KTOT][PITCH]
    float* y1s = sm + KTOT * PITCH;        // 4*64
    float* s2s = y1s + 256;                // 4*4*16
    float* y2s = s2s + 256;                // 4*16

    const int tid  = threadIdx.x;
    const int lane = tid & 31;
    const int wid  = tid >> 5;
    const int bt = blockIdx.x >> 3, ct = blockIdx.x & 7;
    const int tx = tid & 31, ty = tid >> 5;
    const int colbase = ct * 256 + tx * 8;
    const int rowbase = bt * 32 + ty * 4;
    const int ubase   = ct * 64 + tx * 2;

    const float4 bA = *(const float4*)(g_bias + colbase);
    const float4 bB = *(const float4*)(g_bias + colbase + 4);

    // cell state in registers: 4 batch rows x 2 units
    float c0[4], c1[4];
#pragma unroll
    for (int b = 0; b < 4; b++) {
        float2 cv = *(const float2*)(cell + (size_t)(rowbase + b) * HID + ubase);
        c0[b] = cv.x; c1[b] = cv.y;
    }

    unsigned bar = 0;

    for (int t = 0; t < SEQ; t++) {
        // ---------- stage inp k-major into smem ----------
        const int rb = t & 1;
#pragma unroll
        for (int i = 0; i < 4; i++) {
            int b = wid * 4 + i;
            int row = bt * 32 + b;
            const float* xr = x + (size_t)row * SEQ * OBS + (size_t)t * OBS;
            for (int k = lane; k < OBS; k += 32) sa[k * PITCH + b] = xr[k];
            if (lane < 2) sa[(OBS + lane) * PITCH + b] = __ldcg(&g_y[row * 2 + lane]);
            const float* hr = &g_hbuf[rb][(size_t)row * HID];
            for (int k = lane; k < HID; k += 32) sa[(INP + k) * PITCH + b] = __ldcg(&hr[k]);
        }
        __syncthreads();

        // ---------- gates GEMM: 4 batch x 8 cols per thread ----------
        ull acc[4][4];
#pragma unroll
        for (int b = 0; b < 4; b++) {
            acc[b][0] = pack2(bA.x, bA.y);
            acc[b][1] = pack2(bA.z, bA.w);
            acc[b][2] = pack2(bB.x, bB.y);
            acc[b][3] = pack2(bB.z, bB.w);
        }
        const float* wp = g_Wt + colbase;
        const float* ap = sa + ty * 4;
#pragma unroll 2
        for (int k = 0; k < KTOT; k++) {
            float4 w0 = *(const float4*)(wp + (size_t)k * GAT);
            float4 w1 = *(const float4*)(wp + (size_t)k * GAT + 4);
            float4 av = *(const float4*)(ap + k * PITCH);
            ull Wa = pack2(w0.x, w0.y), Wb = pack2(w0.z, w0.w);
            ull Wc = pack2(w1.x, w1.y), Wd = pack2(w1.z, w1.w);
            ull a0 = dup2(av.x), a1 = dup2(av.y), a2 = dup2(av.z), a3 = dup2(av.w);
            fma2(acc[0][0], a0, Wa); fma2(acc[0][1], a0, Wb);
            fma2(acc[0][2], a0, Wc); fma2(acc[0][3], a0, Wd);
            fma2(acc[1][0], a1, Wa); fma2(acc[1][1], a1, Wb);
            fma2(acc[1][2], a1, Wc); fma2(acc[1][3], a1, Wd);
            fma2(acc[2][0], a2, Wa); fma2(acc[2][1], a2, Wb);
            fma2(acc[2][2], a2, Wc); fma2(acc[2][3], a2, Wd);
            fma2(acc[3][0], a3, Wa); fma2(acc[3][1], a3, Wb);
            fma2(acc[3][2], a3, Wc); fma2(acc[3][3], a3, Wd);
        }

        // ---------- cell update (registers) + h write ----------
        const int wb = (t + 1) & 1;
#pragma unroll
        for (int b = 0; b < 4; b++) {
            float2 p0 = unpack2(acc[b][0]);   // unit0: (i,f)
            float2 p1 = unpack2(acc[b][1]);   // unit0: (g,o)
            float2 p2 = unpack2(acc[b][2]);   // unit1: (i,f)
            float2 p3 = unpack2(acc[b][3]);   // unit1: (g,o)
            float nc0 = sigm(p0.y) * c0[b] + sigm(p0.x) * tanh_(p1.x);
            float h0  = sigm(p1.y) * tanh_(nc0);
            float nc1 = sigm(p2.y) * c1[b] + sigm(p2.x) * tanh_(p3.x);
            float h1  = sigm(p3.y) * tanh_(nc1);
            c0[b] = nc0; c1[b] = nc1;
            int row = rowbase + b;
            float2 hv = make_float2(h0, h1);
            __stcg((float2*)&g_hbuf[wb][(size_t)row * HID + ubase], hv);
            if (t == SEQ - 1) {
                *(float2*)&out[OFF_H + (size_t)row * HID + ubase] = hv;
                *(float2*)&out[OFF_C + (size_t)row * HID + ubase] = make_float2(nc0, nc1);
            }
        }

        grid_barrier(++bar);

        // ---------- MLP: each block handles 4 batch rows ----------
        {
            const int rowb = blockIdx.x * 4;
            const float* hb = g_hbuf[wb];
            for (int i = tid; i < 4 * HID; i += NTHR) {
                int r = i >> 9, k = i & (HID - 1);
                sa[i] = __ldcg(&hb[(size_t)(rowb + r) * HID + k]);
            }
            __syncthreads();
            {   // layer 1: H -> 64
                int r = tid >> 6, u = tid & 63;
                const float* hr  = sa + r * HID;
                const float* w1r = W1 + (size_t)u * HID;
                float a0 = __ldg(&b1[u]), a1v = 0.f, a2v = 0.f, a3v = 0.f;
#pragma unroll 4
                for (int k = 0; k < HID; k += 4) {
                    float4 hv = *(const float4*)(hr + k);
                    float4 wv = __ldg((const float4*)(w1r + k));
                    a0  = fmaf(hv.x, wv.x, a0);
                    a1v = fmaf(hv.y, wv.y, a1v);
                    a2v = fmaf(hv.z, wv.z, a2v);
                    a3v = fmaf(hv.w, wv.w, a3v);
                }
                y1s[r * 64 + u] = fmaxf((a0 + a1v) + (a2v + a3v), 0.f);
            }
            __syncthreads();
            {   // layer 2 partials: 64 -> 16
                int r = tid >> 6, ch = (tid >> 4) & 3, u2 = tid & 15;
                const float* yr  = y1s + r * 64 + ch * 16;
                const float* w2r = W2 + u2 * 64 + ch * 16;
                float a2v = 0.f;
#pragma unroll
                for (int kk = 0; kk < 16; kk++) a2v = fmaf(yr[kk], __ldg(&w2r[kk]), a2v);
                s2s[(r * 4 + ch) * 16 + u2] = a2v;
            }
            __syncthreads();
            if (tid < 64) {
                int r = tid >> 4, u2 = tid & 15;
                float v = s2s[(r * 4 + 0) * 16 + u2] + s2s[(r * 4 + 1) * 16 + u2]
                        + s2s[(r * 4 + 2) * 16 + u2] + s2s[(r * 4 + 3) * 16 + u2]
                        + __ldg(&b2[u2]);
                y2s[r * 16 + u2] = fmaxf(v, 0.f);
            }
            __syncthreads();
            if (tid < 8) {  // layer 3: 16 -> 2, write y + output
                int r = tid >> 1, j = tid & 1;
                const float* yr = y2s + r * 16;
                float v = __ldg(&b3[j]);
#pragma unroll
                for (int kk = 0; kk < 16; kk++) v = fmaf(yr[kk], __ldg(&W3[j * 16 + kk]), v);
                v = fmaxf(v, 0.f);
                int row = rowb + r;
                __stcg(&g_y[row * 2 + j], v);
                out[(size_t)row * SEQ * 2 + (size_t)t * 2 + j] = v;
            }
        }

        grid_barrier(++bar);
    }
}

extern "C" void kernel_launch(void* const* d_in, const int* in_sizes, int n_in,
                              void* d_out, int out_size) {
    const float* x      = (const float*)d_in[0];
    const float* pos    = (const float*)d_in[1];
    const float* hidden = (const float*)d_in[2];
    const float* cell   = (const float*)d_in[3];
    const float* W_ih   = (const float*)d_in[4];
    const float* W_hh   = (const float*)d_in[5];
    const float* b_ih   = (const float*)d_in[6];
    const float* b_hh   = (const float*)d_in[7];
    const float* W1     = (const float*)d_in[8];
    const float* b1     = (const float*)d_in[9];
    const float* W2     = (const float*)d_in[10];
    const float* b2     = (const float*)d_in[11];
    const float* W3     = (const float*)d_in[12];
    const float* b3     = (const float*)d_in[13];
    float* out = (float*)d_out;

    cudaFuncSetAttribute((const void*)lstm_persistent,
                         cudaFuncAttributeMaxDynamicSharedMemorySize, SMEM_BYTES);

    precompute_kernel<<<512, 256>>>(W_ih, W_hh, b_ih, b_hh, hidden, pos);
    lstm_persistent<<<NBLK, NTHR, SMEM_BYTES>>>(x, cell, W1, b1, W2, b2, W3, b3, out);
}

// round 5
// speedup vs baseline: 1.4725x; 1.4725x over previous
#include <cuda_runtime.h>
#include <cstdint>

#define BATCH 512
#define SEQ   512
#define OBS   103
#define HID   512
#define INP   105            // OBS + 2 fed-back pos
#define KTOT  617            // INP + HID
#define GAT   2048           // 4*HID
#define NBLK  128
#define NTHR  512
#define PITCH 36             // smem k-row pitch (16B-aligned LDS.128)
#define OFF_H (BATCH*SEQ*2)
#define OFF_C (OFF_H + BATCH*HID)
#define SA_FLOATS (KTOT*PITCH)        // 22212
#define SMEM_FLOATS (SA_FLOATS + 1152)
#define SMEM_BYTES  (SMEM_FLOATS*4)

typedef unsigned long long ull;

// ---- static device scratch (no allocation allowed) ----
__device__ __align__(16) float g_Wt[KTOT*GAT];   // k-major, gate-interleaved cols
__device__ __align__(16) float g_bias[GAT];      // b_ih+b_hh, permuted
__device__ __align__(16) float g_hbuf[2][BATCH*HID];
__device__ __align__(16) float g_y[BATCH*2];
__device__ unsigned g_arrive;
__device__ volatile unsigned g_gen;

// ---- packed f32x2 helpers ----
__device__ __forceinline__ ull dup2(float x) {
    ull r; asm("mov.b64 %0, {%1, %1};" : "=l"(r) : "f"(x)); return r;
}
__device__ __forceinline__ ull pack2(float lo, float hi) {
    ull r; asm("mov.b64 %0, {%1, %2};" : "=l"(r) : "f"(lo), "f"(hi)); return r;
}
__device__ __forceinline__ float2 unpack2(ull v) {
    float lo, hi; asm("mov.b64 {%0, %1}, %2;" : "=f"(lo), "=f"(hi) : "l"(v));
    return make_float2(lo, hi);
}
__device__ __forceinline__ void fma2(ull &d, ull a, ull b) {
    asm("fma.rn.f32x2 %0, %1, %2, %0;" : "+l"(d) : "l"(a), "l"(b));
}

__device__ __forceinline__ float sigm(float x) { return 1.f / (1.f + __expf(-x)); }
__device__ __forceinline__ float tanh_(float x) {
    x = fminf(15.f, fmaxf(-15.f, x));
    float e = __expf(-2.f * x);
    return (1.f - e) / (1.f + e);
}

// ---- grid barrier: all 128 blocks co-resident -> spin is safe ----
__device__ __forceinline__ void grid_barrier(unsigned target) {
    __threadfence();
    __syncthreads();
    if (threadIdx.x == 0) {
        unsigned v = atomicAdd(&g_arrive, 1u);
        if (v == NBLK - 1) {
            g_arrive = 0;
            __threadfence();
            g_gen = target;
        } else {
            while (g_gen < target) __nanosleep(64);
        }
    }
    __syncthreads();
}

// ---- precompute: permuted transpose of W, combined bias, state init ----
__global__ void precompute_kernel(const float* __restrict__ W_ih,
                                  const float* __restrict__ W_hh,
                                  const float* __restrict__ b_ih,
                                  const float* __restrict__ b_hh,
                                  const float* __restrict__ hidden,
                                  const float* __restrict__ pos) {
    const int stride = gridDim.x * blockDim.x;
    const int i0 = blockIdx.x * blockDim.x + threadIdx.x;
    // Wt[k][col]; col = ubp*256 + ul*4 + g  <->  original row r = g*HID + ubp*64 + ul
    for (int idx = i0; idx < KTOT * GAT; idx += stride) {
        int k = idx >> 11, col = idx & 2047;
        int ubp = col >> 8, rem = col & 255, ul = rem >> 2, g = rem & 3;
        int r = g * HID + ubp * 64 + ul;
        g_Wt[idx] = (k < INP) ? W_ih[r * INP + k] : W_hh[r * HID + (k - INP)];
    }
    for (int col = i0; col < GAT; col += stride) {
        int ubp = col >> 8, rem = col & 255, ul = rem >> 2, g = rem & 3;
        int r = g * HID + ubp * 64 + ul;
        g_bias[col] = b_ih[r] + b_hh[r];
    }
    for (int idx = i0; idx < BATCH * HID; idx += stride) g_hbuf[0][idx] = hidden[idx];
    for (int idx = i0; idx < BATCH * 2; idx += stride)
        g_y[idx] = pos[(idx >> 1) * SEQ * 2 + (idx & 1)];   // pos[:,0,:]
    if (i0 == 0) { g_arrive = 0; g_gen = 0; }
}

// ---- persistent LSTM kernel ----
__global__ void __launch_bounds__(NTHR, 1)
lstm_persistent(const float* __restrict__ x,
                const float* __restrict__ cell,
                const float* __restrict__ W1, const float* __restrict__ b1,
                const float* __restrict__ W2, const float* __restrict__ b2,
                const float* __restrict__ W3, const float* __restrict__ b3,
                float* __restrict__ out) {
    extern __shared__ float sm[];
    float* sa  = sm;                       // staged input, k-major [KTOT][PITCH]
    float* p1s = sm + SA_FLOATS;           // 512 layer1 split-K partials
    float* y1s = p1s + 512;                // 4*64
    float* s2p = y1s + 256;                // 4*4*16
    float* y2s = s2p + 256;                // 4*16

    const int tid  = threadIdx.x;
    const int lane = tid & 31;
    const int wid  = tid >> 5;             // 0..15
    const int bt = blockIdx.x >> 3, ct = blockIdx.x & 7;
    const int tx = tid & 63, ty = tid >> 6;   // tx: unit, ty: batch group
    const int colbase = ct * 256 + tx * 4;    // one unit = 4 interleaved gates
    const int rowbase = bt * 32 + ty * 4;
    const int u       = ct * 64 + tx;         // global hidden unit

    const float4 bA = *(const float4*)(g_bias + colbase);

    // cell state in registers: 4 batch rows x 1 unit
    float c[4];
#pragma unroll
    for (int b = 0; b < 4; b++) c[b] = cell[(size_t)(rowbase + b) * HID + u];

    unsigned bar = 0;

    for (int t = 0; t < SEQ; t++) {
        // ---------- stage inp k-major into smem (2 rows per warp) ----------
        const int rb = t & 1;
#pragma unroll
        for (int i = 0; i < 2; i++) {
            int b = wid * 2 + i;
            int row = bt * 32 + b;
            const float* xr = x + (size_t)row * SEQ * OBS + (size_t)t * OBS;
            for (int k = lane; k < OBS; k += 32) sa[k * PITCH + b] = xr[k];
            if (lane < 2) sa[(OBS + lane) * PITCH + b] = __ldcg(&g_y[row * 2 + lane]);
            const float* hr = &g_hbuf[rb][(size_t)row * HID];
            for (int k = lane; k < HID; k += 32) sa[(INP + k) * PITCH + b] = __ldcg(&hr[k]);
        }
        __syncthreads();

        // ---------- gates GEMM: 4 batch x 4 cols (1 unit) per thread ----------
        ull acc[4][2];
#pragma unroll
        for (int b = 0; b < 4; b++) {
            acc[b][0] = pack2(bA.x, bA.y);     // (i,f)
            acc[b][1] = pack2(bA.z, bA.w);     // (g,o)
        }
        const float* wp = g_Wt + colbase;
        const float* ap = sa + ty * 4;

        float4 wbuf[4];
#pragma unroll
        for (int r = 0; r < 4; r++) wbuf[r] = *(const float4*)(wp + (size_t)r * GAT);

#pragma unroll 4
        for (int k = 0; k < KTOT; k++) {
            float4 w  = wbuf[k & 3];
            float4 av = *(const float4*)(ap + k * PITCH);
            int kp = k + 4;
            if (kp < KTOT) wbuf[k & 3] = *(const float4*)(wp + (size_t)kp * GAT);
            ull Wa = pack2(w.x, w.y), Wb = pack2(w.z, w.w);
            ull a0 = dup2(av.x), a1 = dup2(av.y), a2 = dup2(av.z), a3 = dup2(av.w);
            fma2(acc[0][0], a0, Wa); fma2(acc[0][1], a0, Wb);
            fma2(acc[1][0], a1, Wa); fma2(acc[1][1], a1, Wb);
            fma2(acc[2][0], a2, Wa); fma2(acc[2][1], a2, Wb);
            fma2(acc[3][0], a3, Wa); fma2(acc[3][1], a3, Wb);
        }

        // ---------- cell update (registers) + h write ----------
        const int wb = (t + 1) & 1;
#pragma unroll
        for (int b = 0; b < 4; b++) {
            float2 p0 = unpack2(acc[b][0]);   // (i,f)
            float2 p1 = unpack2(acc[b][1]);   // (g,o)
            float nc = sigm(p0.y) * c[b] + sigm(p0.x) * tanh_(p1.x);
            float h  = sigm(p1.y) * tanh_(nc);
            c[b] = nc;
            int row = rowbase + b;
            __stcg(&g_hbuf[wb][(size_t)row * HID + u], h);
            if (t == SEQ - 1) {
                out[OFF_H + (size_t)row * HID + u] = h;
                out[OFF_C + (size_t)row * HID + u] = nc;
            }
        }

        grid_barrier(++bar);

        // ---------- MLP: each block handles 4 batch rows ----------
        {
            const int rowb = blockIdx.x * 4;
            const float* hb = g_hbuf[wb];
            for (int i = tid; i < 4 * HID; i += NTHR) {
                int r = i >> 9, k = i & (HID - 1);
                sa[i] = __ldcg(&hb[(size_t)(rowb + r) * HID + k]);
            }
            __syncthreads();
            {   // layer 1 split-K: (r, u1, half) per thread
                int r = tid >> 7, u1 = (tid >> 1) & 63, half = tid & 1;
                const float* hr  = sa + r * HID + half * 256;
                const float* w1r = W1 + (size_t)u1 * HID + half * 256;
                float a0 = 0.f, a1v = 0.f, a2v = 0.f, a3v = 0.f;
#pragma unroll 4
                for (int k = 0; k < 256; k += 4) {
                    float4 hv = *(const float4*)(hr + k);
                    float4 wv = __ldg((const float4*)(w1r + k));
                    a0  = fmaf(hv.x, wv.x, a0);
                    a1v = fmaf(hv.y, wv.y, a1v);
                    a2v = fmaf(hv.z, wv.z, a2v);
                    a3v = fmaf(hv.w, wv.w, a3v);
                }
                p1s[tid] = (a0 + a1v) + (a2v + a3v);
            }
            __syncthreads();
            if (tid < 256) {   // layer 1 combine + relu
                int r = tid >> 6, u1 = tid & 63;
                int base = r * 128 + u1 * 2;
                y1s[r * 64 + u1] =
                    fmaxf(p1s[base] + p1s[base + 1] + __ldg(&b1[u1]), 0.f);
            }
            __syncthreads();
            if (tid < 256) {   // layer 2 partials: 64 -> 16
                int r = tid >> 6, ch = (tid >> 4) & 3, u2 = tid & 15;
                const float* yr  = y1s + r * 64 + ch * 16;
                const float* w2r = W2 + u2 * 64 + ch * 16;
                float a2v = 0.f;
#pragma unroll
                for (int kk = 0; kk < 16; kk++) a2v = fmaf(yr[kk], __ldg(&w2r[kk]), a2v);
                s2p[(r * 4 + ch) * 16 + u2] = a2v;
            }
            __syncthreads();
            if (tid < 64) {    // layer 2 combine + relu
                int r = tid >> 4, u2 = tid & 15;
                float v = s2p[(r * 4 + 0) * 16 + u2] + s2p[(r * 4 + 1) * 16 + u2]
                        + s2p[(r * 4 + 2) * 16 + u2] + s2p[(r * 4 + 3) * 16 + u2]
                        + __ldg(&b2[u2]);
                y2s[r * 16 + u2] = fmaxf(v, 0.f);
            }
            __syncthreads();
            if (tid < 8) {     // layer 3: 16 -> 2, write y + output
                int r = tid >> 1, j = tid & 1;
                const float* yr = y2s + r * 16;
                float v = __ldg(&b3[j]);
#pragma unroll
                for (int kk = 0; kk < 16; kk++) v = fmaf(yr[kk], __ldg(&W3[j * 16 + kk]), v);
                v = fmaxf(v, 0.f);
                int row = rowb + r;
                __stcg(&g_y[row * 2 + j], v);
                out[(size_t)row * SEQ * 2 + (size_t)t * 2 + j] = v;
            }
        }

        grid_barrier(++bar);
    }
}

extern "C" void kernel_launch(void* const* d_in, const int* in_sizes, int n_in,
                              void* d_out, int out_size) {
    const float* x      = (const float*)d_in[0];
    const float* pos    = (const float*)d_in[1];
    const float* hidden = (const float*)d_in[2];
    const float* cell   = (const float*)d_in[3];
    const float* W_ih   = (const float*)d_in[4];
    const float* W_hh   = (const float*)d_in[5];
    const float* b_ih   = (const float*)d_in[6];
    const float* b_hh   = (const float*)d_in[7];
    const float* W1     = (const float*)d_in[8];
    const float* b1     = (const float*)d_in[9];
    const float* W2     = (const float*)d_in[10];
    const float* b2     = (const float*)d_in[11];
    const float* W3     = (const float*)d_in[12];
    const float* b3     = (const float*)d_in[13];
    float* out = (float*)d_out;

    cudaFuncSetAttribute((const void*)lstm_persistent,
                         cudaFuncAttributeMaxDynamicSharedMemorySize, SMEM_BYTES);

    precompute_kernel<<<512, 256>>>(W_ih, W_hh, b_ih, b_hh, hidden, pos);
    lstm_persistent<<<NBLK, NTHR, SMEM_BYTES>>>(x, cell, W1, b1, W2, b2, W3, b3, out);
}

// round 6
// speedup vs baseline: 1.5920x; 1.0812x over previous
#include <cuda_runtime.h>
#include <cstdint>

#define BATCH 512
#define SEQ   512
#define OBS   103
#define HID   512
#define INP   105            // OBS + 2 fed-back pos
#define KTOT  617            // INP + HID
#define GAT   2048           // 4*HID
#define NBLK  128
#define NTHR  512
#define PITCH 36             // smem k-row pitch (16B-aligned LDS.128)
#define OFF_H (BATCH*SEQ*2)
#define OFF_C (OFF_H + BATCH*HID)
#define SA_FLOATS (KTOT*PITCH)        // 22212
#define SMEM_FLOATS (SA_FLOATS + 2048 + 512 + 256 + 64 + 32)
#define SMEM_BYTES  (SMEM_FLOATS*4)

typedef unsigned long long ull;

// ---- static device scratch (no allocation allowed) ----
__device__ __align__(16) float g_Wt[KTOT*GAT];   // k-major, gate-interleaved cols
__device__ __align__(16) float g_bias[GAT];      // b_ih+b_hh, permuted
__device__ __align__(16) float g_W1t[HID*64];    // layer1 weights, k-major
__device__ __align__(16) float g_W2t[64*16];     // layer2 weights, k-major
__device__ __align__(16) float g_hbuf[2][BATCH*HID];
__device__ __align__(16) float g_y[BATCH*2];
__device__ unsigned g_arrive;
__device__ volatile unsigned g_gen;

// ---- packed f32x2 helpers ----
__device__ __forceinline__ ull dup2(float x) {
    ull r; asm("mov.b64 %0, {%1, %1};" : "=l"(r) : "f"(x)); return r;
}
__device__ __forceinline__ ull pack2(float lo, float hi) {
    ull r; asm("mov.b64 %0, {%1, %2};" : "=l"(r) : "f"(lo), "f"(hi)); return r;
}
__device__ __forceinline__ float2 unpack2(ull v) {
    float lo, hi; asm("mov.b64 {%0, %1}, %2;" : "=f"(lo), "=f"(hi) : "l"(v));
    return make_float2(lo, hi);
}
__device__ __forceinline__ void fma2(ull &d, ull a, ull b) {
    asm("fma.rn.f32x2 %0, %1, %2, %0;" : "+l"(d) : "l"(a), "l"(b));
}

__device__ __forceinline__ float sigm(float x) { return 1.f / (1.f + __expf(-x)); }
__device__ __forceinline__ float tanh_(float x) {
    x = fminf(15.f, fmaxf(-15.f, x));
    float e = __expf(-2.f * x);
    return (1.f - e) / (1.f + e);
}

// ---- grid barrier: all 128 blocks co-resident -> spin is safe ----
__device__ __forceinline__ void grid_barrier(unsigned target) {
    __threadfence();
    __syncthreads();
    if (threadIdx.x == 0) {
        unsigned v = atomicAdd(&g_arrive, 1u);
        if (v == NBLK - 1) {
            g_arrive = 0;
            __threadfence();
            g_gen = target;
        } else {
            while (g_gen < target) { }   // tight spin, L2 poll
        }
    }
    __syncthreads();
}

// ---- precompute: permuted transpose of W, combined bias, state init ----
__global__ void precompute_kernel(const float* __restrict__ W_ih,
                                  const float* __restrict__ W_hh,
                                  const float* __restrict__ b_ih,
                                  const float* __restrict__ b_hh,
                                  const float* __restrict__ hidden,
                                  const float* __restrict__ pos,
                                  const float* __restrict__ W1,
                                  const float* __restrict__ W2) {
    const int stride = gridDim.x * blockDim.x;
    const int i0 = blockIdx.x * blockDim.x + threadIdx.x;
    // Wt[k][col]; col = ubp*256 + ul*4 + g  <->  original row r = g*HID + ubp*64 + ul
    for (int idx = i0; idx < KTOT * GAT; idx += stride) {
        int k = idx >> 11, col = idx & 2047;
        int ubp = col >> 8, rem = col & 255, ul = rem >> 2, g = rem & 3;
        int r = g * HID + ubp * 64 + ul;
        g_Wt[idx] = (k < INP) ? W_ih[r * INP + k] : W_hh[r * HID + (k - INP)];
    }
    for (int col = i0; col < GAT; col += stride) {
        int ubp = col >> 8, rem = col & 255, ul = rem >> 2, g = rem & 3;
        int r = g * HID + ubp * 64 + ul;
        g_bias[col] = b_ih[r] + b_hh[r];
    }
    for (int idx = i0; idx < HID * 64; idx += stride) {
        int k = idx >> 6, u1 = idx & 63;
        g_W1t[idx] = W1[u1 * HID + k];
    }
    for (int idx = i0; idx < 64 * 16; idx += stride) {
        int k = idx >> 4, u2 = idx & 15;
        g_W2t[idx] = W2[u2 * 64 + k];
    }
    for (int idx = i0; idx < BATCH * HID; idx += stride) g_hbuf[0][idx] = hidden[idx];
    for (int idx = i0; idx < BATCH * 2; idx += stride)
        g_y[idx] = pos[(idx >> 1) * SEQ * 2 + (idx & 1)];   // pos[:,0,:]
    if (i0 == 0) { g_arrive = 0; g_gen = 0; }
}

// ---- persistent LSTM kernel ----
__global__ void __launch_bounds__(NTHR, 1)
lstm_persistent(const float* __restrict__ x,
                const float* __restrict__ cell,
                const float* __restrict__ b1,
                const float* __restrict__ b2,
                const float* __restrict__ W3, const float* __restrict__ b3,
                float* __restrict__ out) {
    extern __shared__ float sm[];
    float* sa    = sm;                     // staged input, k-major [KTOT][PITCH]
    float* hbufS = sm + SA_FLOATS;         // 4 MLP rows of h (4*512)
    float* p1s   = hbufS + 2048;           // layer1 split partials (2*4*64)
    float* y1s   = p1s + 512;              // 4*64
    float* y2s   = y1s + 256;              // 4*16

    const int tid  = threadIdx.x;
    const int lane = tid & 31;
    const int wid  = tid >> 5;             // 0..15
    const int bt = blockIdx.x >> 3, ct = blockIdx.x & 7;
    const int tx = tid & 63, ty = tid >> 6;   // tx: unit, ty: batch group
    const int colbase = ct * 256 + tx * 4;    // one unit = 4 interleaved gates
    const int rowbase = bt * 32 + ty * 4;
    const int u       = ct * 64 + tx;         // global hidden unit
    const int mrowb   = blockIdx.x * 4;       // MLP rows for this block

    const float4 bA = *(const float4*)(g_bias + colbase);

    // cell state in registers: 4 batch rows x 1 unit
    float c[4];
#pragma unroll
    for (int b = 0; b < 4; b++) c[b] = cell[(size_t)(rowbase + b) * HID + u];

    unsigned bar = 0;

    // ---------- prologue: stage step-0 input ----------
    {
#pragma unroll
        for (int i = 0; i < 2; i++) {
            int b = wid * 2 + i;
            int row = bt * 32 + b;
            const float* xr = x + (size_t)row * SEQ * OBS;
            for (int k = lane; k < OBS; k += 32) sa[k * PITCH + b] = xr[k];
            if (lane < 2) sa[(OBS + lane) * PITCH + b] = g_y[row * 2 + lane];
            const float* hr = &g_hbuf[0][(size_t)row * HID];
            for (int k = lane; k < HID; k += 32) sa[(INP + k) * PITCH + b] = hr[k];
        }
        __syncthreads();
    }

    for (int t = 0; t < SEQ; t++) {
        // ---------- gates GEMM: 4 batch x 4 cols (1 unit) per thread ----------
        ull acc[4][2];
#pragma unroll
        for (int b = 0; b < 4; b++) {
            acc[b][0] = pack2(bA.x, bA.y);     // (i,f)
            acc[b][1] = pack2(bA.z, bA.w);     // (g,o)
        }
        const float* wp = g_Wt + colbase;
        const float* ap = sa + ty * 4;

        ulonglong2 wbuf[4];
#pragma unroll
        for (int r = 0; r < 4; r++) wbuf[r] = *(const ulonglong2*)(wp + (size_t)r * GAT);

#pragma unroll 4
        for (int k = 0; k < KTOT; k++) {
            ulonglong2 w = wbuf[k & 3];
            float4 av = *(const float4*)(ap + k * PITCH);
            int kp = k + 4;
            if (kp < KTOT) wbuf[k & 3] = *(const ulonglong2*)(wp + (size_t)kp * GAT);
            ull a0 = dup2(av.x), a1 = dup2(av.y), a2 = dup2(av.z), a3 = dup2(av.w);
            fma2(acc[0][0], a0, w.x); fma2(acc[0][1], a0, w.y);
            fma2(acc[1][0], a1, w.x); fma2(acc[1][1], a1, w.y);
            fma2(acc[2][0], a2, w.x); fma2(acc[2][1], a2, w.y);
            fma2(acc[3][0], a3, w.x); fma2(acc[3][1], a3, w.y);
        }

        // ---------- cell update (registers) + h write ----------
        const int wb = (t + 1) & 1;
#pragma unroll
        for (int b = 0; b < 4; b++) {
            float2 p0 = unpack2(acc[b][0]);   // (i,f)
            float2 p1 = unpack2(acc[b][1]);   // (g,o)
            float nc = sigm(p0.y) * c[b] + sigm(p0.x) * tanh_(p1.x);
            float h  = sigm(p1.y) * tanh_(nc);
            c[b] = nc;
            int row = rowbase + b;
            __stcg(&g_hbuf[wb][(size_t)row * HID + u], h);
            if (t == SEQ - 1) {
                out[OFF_H + (size_t)row * HID + u] = h;
                out[OFF_C + (size_t)row * HID + u] = nc;
            }
        }

        grid_barrier(++bar);   // h_t now globally visible

        // ---------- overlapped: stage next step (x,h) + MLP(h_t) ----------
        const float* hb = g_hbuf[wb];

        if (t < SEQ - 1) {     // stage x_{t+1}, h_t (y patched after barrier2)
            int tn = t + 1;
#pragma unroll
            for (int i = 0; i < 2; i++) {
                int b = wid * 2 + i;
                int row = bt * 32 + b;
                const float* xr = x + (size_t)row * SEQ * OBS + (size_t)tn * OBS;
                for (int k = lane; k < OBS; k += 32) sa[k * PITCH + b] = xr[k];
                const float* hr = &hb[(size_t)row * HID];
                for (int k = lane; k < HID; k += 32)
                    sa[(INP + k) * PITCH + b] = __ldcg(&hr[k]);
            }
        }

        // copy 4 MLP rows of h into smem
        for (int i = tid; i < 4 * HID; i += NTHR) {
            int r = i >> 9, k = i & (HID - 1);
            hbufS[i] = __ldcg(&hb[(size_t)(mrowb + r) * HID + k]);
        }
        __syncthreads();

        if (tid < 128) {  // layer 1: thread (half, u1) computes all 4 rows
            int half = tid >> 6, u1 = tid & 63;
            const float* wq = g_W1t + (size_t)(half * 256) * 64 + u1;
            float a0 = 0.f, a1 = 0.f, a2 = 0.f, a3 = 0.f;
            const float* h0 = hbufS + half * 256;
#pragma unroll 4
            for (int k = 0; k < 256; k++) {
                float w = __ldg(wq + (size_t)k * 64);
                a0 = fmaf(h0[k],        w, a0);
                a1 = fmaf(h0[k + 512],  w, a1);
                a2 = fmaf(h0[k + 1024], w, a2);
                a3 = fmaf(h0[k + 1536], w, a3);
            }
            p1s[half * 256 + u1]       = a0;
            p1s[half * 256 + 64 + u1]  = a1;
            p1s[half * 256 + 128 + u1] = a2;
            p1s[half * 256 + 192 + u1] = a3;
        }
        __syncthreads();
        if (tid < 256) {  // layer 1 combine + relu
            int u1 = tid & 63;
            y1s[tid] = fmaxf(p1s[tid] + p1s[256 + tid] + __ldg(&b1[u1]), 0.f);
        }
        __syncthreads();
        if (tid < 64) {   // layer 2: 64 -> 16
            int r = tid >> 4, u2 = tid & 15;
            const float* yr = y1s + r * 64;
            float v = __ldg(&b2[u2]);
#pragma unroll
            for (int kk = 0; kk < 64; kk++)
                v = fmaf(yr[kk], __ldg(&g_W2t[kk * 16 + u2]), v);
            y2s[r * 16 + u2] = fmaxf(v, 0.f);
        }
        __syncthreads();
        if (tid < 8) {    // layer 3: 16 -> 2, write y + output
            int r = tid >> 1, j = tid & 1;
            const float* yr = y2s + r * 16;
            float v = __ldg(&b3[j]);
#pragma unroll
            for (int kk = 0; kk < 16; kk++) v = fmaf(yr[kk], __ldg(&W3[j * 16 + kk]), v);
            v = fmaxf(v, 0.f);
            int row = mrowb + r;
            __stcg(&g_y[row * 2 + j], v);
            out[(size_t)row * SEQ * 2 + (size_t)t * 2 + j] = v;
        }

        if (t < SEQ - 1) {
            grid_barrier(++bar);   // y_t now globally visible
            if (tid < 64) {        // patch fed-back pos into staged input
                int b = tid >> 1, j = tid & 1;
                int row = bt * 32 + b;
                sa[(OBS + j) * PITCH + b] = __ldcg(&g_y[row * 2 + j]);
            }
            __syncthreads();
        }
    }
}

extern "C" void kernel_launch(void* const* d_in, const int* in_sizes, int n_in,
                              void* d_out, int out_size) {
    const float* x      = (const float*)d_in[0];
    const float* pos    = (const float*)d_in[1];
    const float* hidden = (const float*)d_in[2];
    const float* cell   = (const float*)d_in[3];
    const float* W_ih   = (const float*)d_in[4];
    const float* W_hh   = (const float*)d_in[5];
    const float* b_ih   = (const float*)d_in[6];
    const float* b_hh   = (const float*)d_in[7];
    const float* W1     = (const float*)d_in[8];
    const float* b1     = (const float*)d_in[9];
    const float* W2     = (const float*)d_in[10];
    const float* b2     = (const float*)d_in[11];
    const float* W3     = (const float*)d_in[12];
    const float* b3     = (const float*)d_in[13];
    float* out = (float*)d_out;

    cudaFuncSetAttribute((const void*)lstm_persistent,
                         cudaFuncAttributeMaxDynamicSharedMemorySize, SMEM_BYTES);

    precompute_kernel<<<512, 256>>>(W_ih, W_hh, b_ih, b_hh, hidden, pos, W1, W2);
    lstm_persistent<<<NBLK, NTHR, SMEM_BYTES>>>(x, cell, b1, b2, W3, b3, out);
}

// round 7
// speedup vs baseline: 1.8350x; 1.1527x over previous
#include <cuda_runtime.h>
#include <cstdint>

#define BATCH 512
#define SEQ   512
#define OBS   103
#define HID   512
#define INP   105            // OBS + 2 fed-back pos
#define KTOT  617            // INP + HID
#define GAT   2048           // 4*HID
#define NBLK  128
#define NTHR  512
#define PITCHD 68            // dup'd smem k-row pitch (64 dup floats + pad, 16B-aligned)
#define OFF_H (BATCH*SEQ*2)
#define OFF_C (OFF_H + BATCH*HID)
#define SA_FLOATS (KTOT*PITCHD)       // 41956
#define SMEM_FLOATS (SA_FLOATS + 2048 + 2048 + 256 + 64)
#define SMEM_BYTES  (SMEM_FLOATS*4)   // ~185.6 KB

typedef unsigned long long ull;

// ---- static device scratch (no allocation allowed) ----
__device__ __align__(16) float g_Wt[KTOT*GAT];   // k-major, gate-interleaved cols
__device__ __align__(16) float g_bias[GAT];      // b_ih+b_hh, permuted
__device__ __align__(16) float g_W1t[HID*64];    // layer1 weights, k-major
__device__ __align__(16) float g_W2t[64*16];     // layer2 weights, k-major
__device__ __align__(16) float g_hbuf[2][BATCH*HID];
__device__ __align__(16) float g_y[BATCH*2];
__device__ unsigned g_arrive;
__device__ volatile unsigned g_gen;

// ---- packed f32x2 helpers ----
__device__ __forceinline__ ull pack2(float lo, float hi) {
    ull r; asm("mov.b64 %0, {%1, %2};" : "=l"(r) : "f"(lo), "f"(hi)); return r;
}
__device__ __forceinline__ float2 unpack2(ull v) {
    float lo, hi; asm("mov.b64 {%0, %1}, %2;" : "=f"(lo), "=f"(hi) : "l"(v));
    return make_float2(lo, hi);
}
__device__ __forceinline__ void fma2(ull &d, ull a, ull b) {
    asm("fma.rn.f32x2 %0, %1, %2, %0;" : "+l"(d) : "l"(a), "l"(b));
}

__device__ __forceinline__ float sigm(float x) { return 1.f / (1.f + __expf(-x)); }
__device__ __forceinline__ float tanh_(float x) {
    x = fminf(15.f, fmaxf(-15.f, x));
    float e = __expf(-2.f * x);
    return (1.f - e) / (1.f + e);
}

// ---- grid barrier: all 128 blocks co-resident -> spin is safe ----
__device__ __forceinline__ void grid_barrier(unsigned target) {
    __threadfence();
    __syncthreads();
    if (threadIdx.x == 0) {
        unsigned v = atomicAdd(&g_arrive, 1u);
        if (v == NBLK - 1) {
            g_arrive = 0;
            __threadfence();
            g_gen = target;
        } else {
            while (g_gen < target) { }   // tight spin on L2
        }
    }
    __syncthreads();
}

// ---- precompute: permuted transpose of W, combined bias, state init ----
__global__ void precompute_kernel(const float* __restrict__ W_ih,
                                  const float* __restrict__ W_hh,
                                  const float* __restrict__ b_ih,
                                  const float* __restrict__ b_hh,
                                  const float* __restrict__ hidden,
                                  const float* __restrict__ pos,
                                  const float* __restrict__ W1,
                                  const float* __restrict__ W2) {
    const int stride = gridDim.x * blockDim.x;
    const int i0 = blockIdx.x * blockDim.x + threadIdx.x;
    // Wt[k][col]; col = ubp*256 + ul*4 + g  <->  original row r = g*HID + ubp*64 + ul
    for (int idx = i0; idx < KTOT * GAT; idx += stride) {
        int k = idx >> 11, col = idx & 2047;
        int ubp = col >> 8, rem = col & 255, ul = rem >> 2, g = rem & 3;
        int r = g * HID + ubp * 64 + ul;
        g_Wt[idx] = (k < INP) ? W_ih[r * INP + k] : W_hh[r * HID + (k - INP)];
    }
    for (int col = i0; col < GAT; col += stride) {
        int ubp = col >> 8, rem = col & 255, ul = rem >> 2, g = rem & 3;
        int r = g * HID + ubp * 64 + ul;
        g_bias[col] = b_ih[r] + b_hh[r];
    }
    for (int idx = i0; idx < HID * 64; idx += stride) {
        int k = idx >> 6, u1 = idx & 63;
        g_W1t[idx] = W1[u1 * HID + k];
    }
    for (int idx = i0; idx < 64 * 16; idx += stride) {
        int k = idx >> 4, u2 = idx & 15;
        g_W2t[idx] = W2[u2 * 64 + k];
    }
    for (int idx = i0; idx < BATCH * HID; idx += stride) g_hbuf[0][idx] = hidden[idx];
    for (int idx = i0; idx < BATCH * 2; idx += stride)
        g_y[idx] = pos[(idx >> 1) * SEQ * 2 + (idx & 1)];   // pos[:,0,:]
    if (i0 == 0) { g_arrive = 0; g_gen = 0; }
}

// ---- persistent LSTM kernel ----
__global__ void __launch_bounds__(NTHR, 1)
lstm_persistent(const float* __restrict__ x,
                const float* __restrict__ cell,
                const float* __restrict__ b1,
                const float* __restrict__ b2,
                const float* __restrict__ W3, const float* __restrict__ b3,
                float* __restrict__ out) {
    extern __shared__ float sm[];
    float* sa    = sm;                     // staged input DUPLICATED, [KTOT][PITCHD]
    float* hbufS = sm + SA_FLOATS;         // MLP h, transposed [512 k][4 rows]
    float* p1s   = hbufS + 2048;           // layer1 partials [8 ks][4 r][64 u1]
    float* y1s   = p1s + 2048;             // 4*64
    float* y2s   = y1s + 256;              // 4*16

    const int tid  = threadIdx.x;
    const int lane = tid & 31;
    const int wid  = tid >> 5;             // 0..15
    const int bt = blockIdx.x >> 3, ct = blockIdx.x & 7;
    const int tx = tid & 63, ty = tid >> 6;   // tx: unit, ty: batch group
    const int colbase = ct * 256 + tx * 4;    // one unit = 4 interleaved gates
    const int rowbase = bt * 32 + ty * 4;
    const int u       = ct * 64 + tx;         // global hidden unit
    const int mrowb   = blockIdx.x * 4;       // MLP rows for this block

    const float4 bA = *(const float4*)(g_bias + colbase);

    // cell state in registers: 4 batch rows x 1 unit
    float c[4];
#pragma unroll
    for (int b = 0; b < 4; b++) c[b] = cell[(size_t)(rowbase + b) * HID + u];

    unsigned bar = 0;

    // ---------- prologue: stage step-0 input (duplicated pairs) ----------
    {
#pragma unroll
        for (int i = 0; i < 2; i++) {
            int b = wid * 2 + i;
            int row = bt * 32 + b;
            const float* xr = x + (size_t)row * SEQ * OBS;
            for (int k = lane; k < OBS; k += 32) {
                float v = xr[k];
                *(float2*)&sa[k * PITCHD + 2 * b] = make_float2(v, v);
            }
            if (lane < 2) {
                float v = g_y[row * 2 + lane];
                *(float2*)&sa[(OBS + lane) * PITCHD + 2 * b] = make_float2(v, v);
            }
            const float* hr = &g_hbuf[0][(size_t)row * HID];
            for (int k = lane; k < HID; k += 32) {
                float v = hr[k];
                *(float2*)&sa[(INP + k) * PITCHD + 2 * b] = make_float2(v, v);
            }
        }
        __syncthreads();
    }

    for (int t = 0; t < SEQ; t++) {
        // ---------- gates GEMM: 4 batch x 4 cols per thread, zero-MOV ----------
        ull acc[4][2];
#pragma unroll
        for (int b = 0; b < 4; b++) {
            acc[b][0] = pack2(bA.x, bA.y);     // (i,f)
            acc[b][1] = pack2(bA.z, bA.w);     // (g,o)
        }
        const float* wp = g_Wt + colbase;
        const float* ap = sa + ty * 8;         // pairs: (a0,a0,a1,a1) / (a2,a2,a3,a3)

        ulonglong2 wbuf[4];
#pragma unroll
        for (int r = 0; r < 4; r++) wbuf[r] = *(const ulonglong2*)(wp + (size_t)r * GAT);

#pragma unroll 4
        for (int k = 0; k < KTOT; k++) {
            ulonglong2 w   = wbuf[k & 3];
            ulonglong2 A01 = *(const ulonglong2*)(ap + k * PITCHD);       // dup a0,a1
            ulonglong2 A23 = *(const ulonglong2*)(ap + k * PITCHD + 4);   // dup a2,a3
            int kp = k + 4;
            if (kp < KTOT) wbuf[k & 3] = *(const ulonglong2*)(wp + (size_t)kp * GAT);
            fma2(acc[0][0], A01.x, w.x); fma2(acc[0][1], A01.x, w.y);
            fma2(acc[1][0], A01.y, w.x); fma2(acc[1][1], A01.y, w.y);
            fma2(acc[2][0], A23.x, w.x); fma2(acc[2][1], A23.x, w.y);
            fma2(acc[3][0], A23.y, w.x); fma2(acc[3][1], A23.y, w.y);
        }

        // ---------- cell update (registers) + h write ----------
        const int wb = (t + 1) & 1;
#pragma unroll
        for (int b = 0; b < 4; b++) {
            float2 p0 = unpack2(acc[b][0]);   // (i,f)
            float2 p1 = unpack2(acc[b][1]);   // (g,o)
            float nc = sigm(p0.y) * c[b] + sigm(p0.x) * tanh_(p1.x);
            float h  = sigm(p1.y) * tanh_(nc);
            c[b] = nc;
            int row = rowbase + b;
            __stcg(&g_hbuf[wb][(size_t)row * HID + u], h);
            if (t == SEQ - 1) {
                out[OFF_H + (size_t)row * HID + u] = h;
                out[OFF_C + (size_t)row * HID + u] = nc;
            }
        }

        grid_barrier(++bar);   // h_t now globally visible

        // ---------- overlapped: stage next step (x,h) + MLP(h_t) ----------
        const float* hb = g_hbuf[wb];

        if (t < SEQ - 1) {     // stage x_{t+1}, h_t (y patched after barrier2)
            int tn = t + 1;
#pragma unroll
            for (int i = 0; i < 2; i++) {
                int b = wid * 2 + i;
                int row = bt * 32 + b;
                const float* xr = x + (size_t)row * SEQ * OBS + (size_t)tn * OBS;
                for (int k = lane; k < OBS; k += 32) {
                    float v = xr[k];
                    *(float2*)&sa[k * PITCHD + 2 * b] = make_float2(v, v);
                }
                const float* hr = &hb[(size_t)row * HID];
                for (int k = lane; k < HID; k += 32) {
                    float v = __ldcg(&hr[k]);
                    *(float2*)&sa[(INP + k) * PITCHD + 2 * b] = make_float2(v, v);
                }
            }
        }

        // copy 4 MLP rows of h into smem, transposed [k][r]
        for (int i = tid; i < 4 * HID; i += NTHR) {
            int r = i >> 9, k = i & (HID - 1);
            hbufS[k * 4 + r] = __ldcg(&hb[(size_t)(mrowb + r) * HID + k]);
        }
        __syncthreads();

        {   // layer 1: all 512 threads, 8-way k-split; thread=(ks,u1), 4 rows each
            int ks = tid >> 6, u1 = tid & 63;
            const float* wq = g_W1t + (size_t)(ks * 64) * 64 + u1;
            const float* hq = hbufS + ks * 64 * 4;
            float a0 = 0.f, a1 = 0.f, a2 = 0.f, a3 = 0.f;
#pragma unroll 4
            for (int kk = 0; kk < 64; kk++) {
                float w = __ldg(wq + (size_t)kk * 64);
                float4 hv = *(const float4*)(hq + kk * 4);   // broadcast LDS.128
                a0 = fmaf(hv.x, w, a0);
                a1 = fmaf(hv.y, w, a1);
                a2 = fmaf(hv.z, w, a2);
                a3 = fmaf(hv.w, w, a3);
            }
            float* pp = p1s + ks * 256 + u1;
            pp[0]   = a0;
            pp[64]  = a1;
            pp[128] = a2;
            pp[192] = a3;
        }
        __syncthreads();
        if (tid < 256) {  // layer 1 combine + relu
            int r = tid >> 6, u1 = tid & 63;
            float v = __ldg(&b1[u1]);
#pragma unroll
            for (int ks = 0; ks < 8; ks++) v += p1s[ks * 256 + r * 64 + u1];
            y1s[r * 64 + u1] = fmaxf(v, 0.f);
        }
        __syncthreads();
        if (tid < 64) {   // layer 2: 64 -> 16
            int r = tid >> 4, u2 = tid & 15;
            const float* yr = y1s + r * 64;
            float v = __ldg(&b2[u2]);
#pragma unroll
            for (int kk = 0; kk < 64; kk++)
                v = fmaf(yr[kk], __ldg(&g_W2t[kk * 16 + u2]), v);
            y2s[r * 16 + u2] = fmaxf(v, 0.f);
        }
        __syncthreads();
        if (tid < 8) {    // layer 3: 16 -> 2, write y + output
            int r = tid >> 1, j = tid & 1;
            const float* yr = y2s + r * 16;
            float v = __ldg(&b3[j]);
#pragma unroll
            for (int kk = 0; kk < 16; kk++) v = fmaf(yr[kk], __ldg(&W3[j * 16 + kk]), v);
            v = fmaxf(v, 0.f);
            int row = mrowb + r;
            __stcg(&g_y[row * 2 + j], v);
            out[(size_t)row * SEQ * 2 + (size_t)t * 2 + j] = v;
        }

        if (t < SEQ - 1) {
            grid_barrier(++bar);   // y_t now globally visible
            if (tid < 64) {        // patch fed-back pos (duplicated) into staged input
                int b = tid >> 1, j = tid & 1;
                int row = bt * 32 + b;
                float v = __ldcg(&g_y[row * 2 + j]);
                *(float2*)&sa[(OBS + j) * PITCHD + 2 * b] = make_float2(v, v);
            }
            __syncthreads();
        }
    }
}

extern "C" void kernel_launch(void* const* d_in, const int* in_sizes, int n_in,
                              void* d_out, int out_size) {
    const float* x      = (const float*)d_in[0];
    const float* pos    = (const float*)d_in[1];
    const float* hidden = (const float*)d_in[2];
    const float* cell   = (const float*)d_in[3];
    const float* W_ih   = (const float*)d_in[4];
    const float* W_hh   = (const float*)d_in[5];
    const float* b_ih   = (const float*)d_in[6];
    const float* b_hh   = (const float*)d_in[7];
    const float* W1     = (const float*)d_in[8];
    const float* b1     = (const float*)d_in[9];
    const float* W2     = (const float*)d_in[10];
    const float* b2     = (const float*)d_in[11];
    const float* W3     = (const float*)d_in[12];
    const float* b3     = (const float*)d_in[13];
    float* out = (float*)d_out;

    cudaFuncSetAttribute((const void*)lstm_persistent,
                         cudaFuncAttributeMaxDynamicSharedMemorySize, SMEM_BYTES);

    precompute_kernel<<<512, 256>>>(W_ih, W_hh, b_ih, b_hh, hidden, pos, W1, W2);
    lstm_persistent<<<NBLK, NTHR, SMEM_BYTES>>>(x, cell, b1, b2, W3, b3, out);
}